// round 16
// baseline (speedup 1.0000x reference)
#include <cuda_runtime.h>
#include <cstdint>

constexpr int kB  = 16;
constexpr int kTx = 256;
constexpr int kTy = 2048;
constexpr int kC  = 80;
constexpr int kC2 = kC / 2;   // 40 c-pairs
constexpr int kH  = 256;
#define NEGV (-1e9f)
typedef unsigned long long ull;

// ---------------- scratch (__device__ globals) --------------------------------
__device__ float2 g_Ip  [kB * kC2 * kTx];            // (iv[2c], iv[2c+1]) per x
__device__ float2 g_A2p [kB * kC2 * kTx];            // (-2*mu*iv) pairs
__device__ float  g_bias[kB * kTx];
__device__ float  g_logpT[(size_t)kB * kTy * kTx + 40 * kTx];  // [b][t][x] + pad
__device__ int    g_cum [kB * 257];
__device__ int    g_xidx[kB * kTy];

#define FMA2(d,a,b,c) asm("fma.rn.f32x2 %0, %1, %2, %3;" : "=l"(d) : "l"(a), "l"(b), "l"(c))

// ---------------- Kernel 0: per-(b,x) precompute ------------------------------
__global__ void k_prep(const float* __restrict__ mu, const float* __restrict__ ls) {
    int b = blockIdx.x;
    int x = threadIdx.x;
    const float* mub = mu + (size_t)b * kC * kTx + x;
    const float* lsb = ls + (size_t)b * kC * kTx + x;
    float t3 = 0.f, sls = 0.f;
    #pragma unroll 4
    for (int c2 = 0; c2 < kC2; c2++) {
        float m0 = mub[(2 * c2) * kTx],     m1 = mub[(2 * c2 + 1) * kTx];
        float l0 = lsb[(2 * c2) * kTx],     l1 = lsb[(2 * c2 + 1) * kTx];
        float iv0 = expf(-2.0f * l0),       iv1 = expf(-2.0f * l1);
        g_Ip [(b * kC2 + c2) * kTx + x] = make_float2(iv0, iv1);
        g_A2p[(b * kC2 + c2) * kTx + x] = make_float2(-2.0f * m0 * iv0, -2.0f * m1 * iv1);
        t3  += m0 * m0 * iv0 + m1 * m1 * iv1;
        sls += l0 + l1;
    }
    g_bias[b * kTx + x] = -(0.5f / (float)kC) * (t3 + sls);
}

// ---------------- Kernel 1: logp GEMM (R8-exact, best measured 105.4us) --------
// Tile 64x × 128t per block, 256 threads = 16 x-groups(4x) × 16 t-groups(8t).
constexpr int SY_OFF  = 0;
constexpr int SI_OFF  = 40 * 160;
constexpr int SA_OFF  = SI_OFF + 40 * 80;
constexpr int SMEM_ULL = SA_OFF + 40 * 80;          // 12800 ull = 102400 B

__global__ void __launch_bounds__(256) k_logp(const float* __restrict__ y,
                                              float* __restrict__ out_logp) {
    extern __shared__ ull sm[];
    int b  = blockIdx.z;
    int x0 = blockIdx.y * 64;
    int t0 = blockIdx.x * 128;
    int tid = threadIdx.x;
    int tx = tid & 15;        // x-group (16 groups of 4 x)
    int ty = tid >> 4;        // t-group (16 groups of 8 t)

    for (int e = tid; e < 128 * kC2; e += 256) {
        int c2 = e % kC2;
        int t  = e / kC2;
        float2 v = *(const float2*)(y + ((size_t)(b * kTy + t0 + t)) * kC + 2 * c2);
        sm[SY_OFF + c2 * 160 + (t >> 3) * 10 + (t & 7)] = *(ull*)&v;
    }
    for (int e = tid; e < kC2 * 64; e += 256) {
        int c2 = e >> 6, xx = e & 63;
        int sidx = c2 * 80 + (xx >> 3) * 10 + (xx & 7);
        float2 vi = g_Ip [(b * kC2 + c2) * kTx + x0 + xx];
        float2 va = g_A2p[(b * kC2 + c2) * kTx + x0 + xx];
        sm[SI_OFF + sidx] = *(ull*)&vi;
        sm[SA_OFF + sidx] = *(ull*)&va;
    }
    __syncthreads();

    ull acc[4][8];
    #pragma unroll
    for (int i = 0; i < 4; i++)
        #pragma unroll
        for (int j = 0; j < 8; j++) acc[i][j] = 0ull;

    int txoff = ((tx * 4) >> 3) * 10 + ((tx * 4) & 7);

    #pragma unroll 2
    for (int c2 = 0; c2 < kC2; c2++) {
        ull ivp[4], a2p[4], yvp[8];
        const ulonglong2* pi = (const ulonglong2*)(sm + SI_OFF + c2 * 80 + txoff);
        const ulonglong2* pa = (const ulonglong2*)(sm + SA_OFF + c2 * 80 + txoff);
        const ulonglong2* py = (const ulonglong2*)(sm + SY_OFF + c2 * 160 + ty * 10);
        {
            ulonglong2 q;
            q = pi[0]; ivp[0] = q.x; ivp[1] = q.y;
            q = pi[1]; ivp[2] = q.x; ivp[3] = q.y;
            q = pa[0]; a2p[0] = q.x; a2p[1] = q.y;
            q = pa[1]; a2p[2] = q.x; a2p[3] = q.y;
        }
        #pragma unroll
        for (int i = 0; i < 4; i++) {
            ulonglong2 q = py[i];
            yvp[2 * i] = q.x; yvp[2 * i + 1] = q.y;
        }
        #pragma unroll
        for (int xi = 0; xi < 4; xi++)
            #pragma unroll
            for (int ti = 0; ti < 8; ti++) {
                ull tmp;
                FMA2(tmp, ivp[xi], yvp[ti], a2p[xi]);
                FMA2(acc[xi][ti], yvp[ti], tmp, acc[xi][ti]);
            }
    }

    const float SC = -0.5f / (float)kC;
    float res[4][8];
    #pragma unroll
    for (int xi = 0; xi < 4; xi++) {
        float bsv = g_bias[b * kTx + x0 + tx * 4 + xi];
        #pragma unroll
        for (int ti = 0; ti < 8; ti++) {
            float2 p = *(float2*)&acc[xi][ti];
            res[xi][ti] = __fmaf_rn(SC, p.x + p.y, bsv);
        }
    }
    #pragma unroll
    for (int xi = 0; xi < 4; xi++) {
        int x = x0 + tx * 4 + xi;
        float* o = out_logp + ((size_t)(b * kTx + x)) * kTy + t0 + ty * 8;
        float4 r;
        r.x = res[xi][0]; r.y = res[xi][1]; r.z = res[xi][2]; r.w = res[xi][3];
        __stcs((float4*)o, r);
        r.x = res[xi][4]; r.y = res[xi][5]; r.z = res[xi][6]; r.w = res[xi][7];
        __stcs((float4*)(o + 4), r);
    }
    #pragma unroll
    for (int ti = 0; ti < 8; ti++) {
        int t = t0 + ty * 8 + ti;
        float* o = g_logpT + ((size_t)b * kTy + t) * kTx + x0 + tx * 4;
        float4 r;
        r.x = res[0][ti]; r.y = res[1][ti]; r.z = res[2][ti]; r.w = res[3][ti];
        *(float4*)o = r;
    }
}

// ---------------- Kernel 2: MAS, 4-warp chunked-diagonal, chunk=64 -------------
// R10 topology (2 rows/lane, proven recurrence), chunk reduced 128->64:
// 35 phases, pipeline utilization 84% -> 91%. Boundary-prefetch safety holds:
// s_bnd[tbase+64] is written by warp w-1 in phase p-1, consumed in phase p+1.
constexpr int SD_WORDS = 64 * kTx;
constexpr int BND_N    = 2056;

__global__ void __launch_bounds__(256) k_mas(const int* __restrict__ xlv,
                                             const int* __restrict__ ylv,
                                             float* __restrict__ dr_out) {
    extern __shared__ unsigned sdiag[];
    __shared__ float s_bnd[4][BND_N];
    __shared__ int s_dr[kTx];
    __shared__ int s_wsum[8];
    __shared__ int s_tot;
    int b = blockIdx.x;
    int tid = threadIdx.x;
    int w = tid >> 5, lane = tid & 31;

    s_dr[tid] = 0;
    for (int e = tid; e < BND_N; e += 256) s_bnd[3][e] = NEGV;
    if (tid < 3) s_bnd[tid][0] = NEGV;
    __syncthreads();

    float v0, v1, sh_next, bvn;
    float2 buf[32];
    unsigned bits0 = 0u, bits1 = 0u;
    const float* lp = nullptr;
    const float* cons = nullptr;
    bool doProd = false;
    int r0 = 0;

    if (w < 4) {
        r0 = w * 64 + lane * 2;
        lp = g_logpT + (size_t)b * kTy * kTx + r0;
        cons = (w == 0) ? s_bnd[3] : s_bnd[w - 1];
        doProd = (w < 3) && (lane == 31);
        v0 = (r0 == 0) ? 0.f : NEGV;
        v1 = NEGV;
        #pragma unroll
        for (int i = 0; i < 32; i++) buf[i] = *(const float2*)(lp + (size_t)i * kTx);
        sh_next = __shfl_up_sync(0xffffffffu, v1, 1);
        bvn = cons[0];
    }

    for (int p = 0; p < 35; p++) {                   // 32 chunks of 64 + 3 fill
        int c = p - w;
        if (w < 4 && c >= 0 && c < 32) {
            int tbase = c * 64;
            for (int j0 = 0; j0 < 64; j0 += 32) {
                int tb = tbase + j0;
                #pragma unroll
                for (int jj = 0; jj < 32; jj++) {
                    int t = tb + jj;
                    float2 col = buf[jj];
                    buf[jj] = *(const float2*)(lp + (size_t)(t + 32) * kTx);
                    float bv = bvn;
                    bvn = cons[t + 1];
                    float pv0 = (lane == 0) ? bv : sh_next;
                    float pv1 = v0;
                    if (pv0 > v0) bits0 |= (1u << jj);
                    if (pv1 > v1) bits1 |= (1u << jj);
                    v0 = fmaxf(pv0, v0) + col.x;
                    v1 = fmaxf(pv1, v1) + col.y;
                    sh_next = __shfl_up_sync(0xffffffffu, v1, 1);
                    if (doProd) s_bnd[w][t + 1] = v1;
                }
                *(ull*)&sdiag[(tb >> 5) * kTx + r0] = (ull)bits0 | ((ull)bits1 << 32);
                bits0 = bits1 = 0u;
            }
        }
        __syncthreads();
    }

    if (tid == 0) {
        int xlen = xlv[b], ylen = ylv[b];
        int i = xlen - 1;
        int t = ylen - 1;
        while (i > 0 && t >= 0) {
            int wd = t >> 5;
            unsigned word = sdiag[wd * kTx + i] & (0xFFFFFFFFu >> (31 - (t & 31)));
            int tp = -1;
            while (true) {
                if (word) { tp = (wd << 5) + (31 - __clz(word)); break; }
                if (--wd < 0) break;
                word = sdiag[wd * kTx + i];
            }
            if (tp < 0) { s_dr[i] = t + 1; t = -1; break; }
            s_dr[i] = t - tp + 1;
            t = tp - 1;
            i--;
        }
        if (i == 0 && t >= 0) s_dr[0] = t + 1;
    }
    __syncthreads();

    int dv = s_dr[tid];
    int sl = tid & 31, sw = tid >> 5;
    int xs = dv;
    #pragma unroll
    for (int off = 1; off < 32; off <<= 1) {
        int n = __shfl_up_sync(0xffffffffu, xs, off);
        if (sl >= off) xs += n;
    }
    if (sl == 31) s_wsum[sw] = xs;
    __syncthreads();
    if (tid == 0) {
        int a = 0;
        #pragma unroll
        for (int q = 0; q < 8; q++) { int tmp = s_wsum[q]; s_wsum[q] = a; a += tmp; }
        s_tot = a;
    }
    __syncthreads();
    int incl = xs + s_wsum[sw];
    int excl = incl - dv;

    dr_out[b * kTx + tid] = (float)dv;
    g_cum[b * 257 + tid] = excl;
    if (tid == kTx - 1) g_cum[b * 257 + kTx] = incl;

    for (int t = excl; t < excl + dv; t++) g_xidx[b * kTy + t] = tid;
    int total = s_tot;
    for (int t = total + tid; t < kTy; t += 256) g_xidx[b * kTy + t] = -1;
}

// ---------------- Kernel 3: fused attn + o_en gather (proven) ------------------
__global__ void __launch_bounds__(256) k_post(const float* __restrict__ en,
                                              float* __restrict__ oex,
                                              float* __restrict__ attn) {
    int b = blockIdx.y;
    int tid = threadIdx.x;

    if (blockIdx.x < 32) {
        __shared__ __align__(16) float srow[8][kTx];
        __shared__ __align__(16) int   sidx[kTy];
        int h0 = blockIdx.x * 8;

        for (int e = tid; e < 8 * kTx; e += 256) {
            int hh = e >> 8, xx = e & 255;
            srow[hh][xx] = en[((size_t)(b * kH + h0 + hh)) * kTx + xx];
        }
        const int* xsrc = g_xidx + b * kTy;
        for (int e = tid; e < kTy; e += 256) sidx[e] = xsrc[e];
        __syncthreads();

        int4 ia = *(const int4*)&sidx[tid * 8];
        int4 ib = *(const int4*)&sidx[tid * 8 + 4];
        #pragma unroll
        for (int hh = 0; hh < 8; hh++) {
            float* o = oex + ((size_t)(b * kH + h0 + hh)) * kTy + tid * 8;
            const float* sr = srow[hh];
            float4 r;
            r.x = (ia.x >= 0) ? sr[ia.x] : 0.f;
            r.y = (ia.y >= 0) ? sr[ia.y] : 0.f;
            r.z = (ia.z >= 0) ? sr[ia.z] : 0.f;
            r.w = (ia.w >= 0) ? sr[ia.w] : 0.f;
            __stcs((float4*)o, r);
            r.x = (ib.x >= 0) ? sr[ib.x] : 0.f;
            r.y = (ib.y >= 0) ? sr[ib.y] : 0.f;
            r.z = (ib.z >= 0) ? sr[ib.z] : 0.f;
            r.w = (ib.w >= 0) ? sr[ib.w] : 0.f;
            __stcs((float4*)(o + 4), r);
        }
    } else {
        int seg = blockIdx.x - 32;
        int t = tid * 8;
        #pragma unroll 4
        for (int r = 0; r < 16; r++) {
            int x = seg * 16 + r;
            int lo = g_cum[b * 257 + x];
            int hi = g_cum[b * 257 + x + 1];
            float* o = attn + ((size_t)(b * kTx + x)) * kTy + t;
            float4 q;
            q.x = (t + 0 >= lo && t + 0 < hi) ? 1.f : 0.f;
            q.y = (t + 1 >= lo && t + 1 < hi) ? 1.f : 0.f;
            q.z = (t + 2 >= lo && t + 2 < hi) ? 1.f : 0.f;
            q.w = (t + 3 >= lo && t + 3 < hi) ? 1.f : 0.f;
            __stcs((float4*)o, q);
            q.x = (t + 4 >= lo && t + 4 < hi) ? 1.f : 0.f;
            q.y = (t + 5 >= lo && t + 5 < hi) ? 1.f : 0.f;
            q.z = (t + 6 >= lo && t + 6 < hi) ? 1.f : 0.f;
            q.w = (t + 7 >= lo && t + 7 < hi) ? 1.f : 0.f;
            __stcs((float4*)(o + 4), q);
        }
    }
}

// ---------------- launch --------------------------------------------------------
extern "C" void kernel_launch(void* const* d_in, const int* in_sizes, int n_in,
                              void* d_out, int out_size) {
    const float* en = (const float*)d_in[0];   // [B,H,Tx]
    const float* mu = (const float*)d_in[1];   // [B,C,Tx]
    const float* ls = (const float*)d_in[2];   // [B,C,Tx]
    const float* y  = (const float*)d_in[3];   // [B,Ty,C]
    const int*   xl = (const int*)d_in[4];     // [B]
    const int*   yl = (const int*)d_in[5];     // [B]

    float* out   = (float*)d_out;
    float* o_en  = out;                                     // B*H*Ty
    float* attn  = o_en + (size_t)kB * kH * kTy;            // B*Tx*Ty
    float* dr    = attn + (size_t)kB * kTx * kTy;           // B*Tx
    float* logp  = dr + (size_t)kB * kTx;                   // B*Tx*Ty

    cudaFuncSetAttribute(k_logp, cudaFuncAttributeMaxDynamicSharedMemorySize,
                         SMEM_ULL * 8);
    cudaFuncSetAttribute(k_mas, cudaFuncAttributeMaxDynamicSharedMemorySize,
                         SD_WORDS * 4);

    k_prep<<<kB, kTx>>>(mu, ls);
    k_logp<<<dim3(kTy / 128, kTx / 64, kB), 256, SMEM_ULL * 8>>>(y, logp);
    k_mas<<<kB, 256, SD_WORDS * 4>>>(xl, yl, dr);
    k_post<<<dim3(48, kB), 256>>>(en, o_en, attn);
}

// round 17
// speedup vs baseline: 1.1180x; 1.1180x over previous
#include <cuda_runtime.h>
#include <cstdint>

constexpr int kB  = 16;
constexpr int kTx = 256;
constexpr int kTy = 2048;
constexpr int kC  = 80;
constexpr int kC2 = kC / 2;   // 40 c-pairs
constexpr int kH  = 256;
#define NEGV (-1e9f)
typedef unsigned long long ull;

// ---------------- scratch (__device__ globals) --------------------------------
__device__ float2 g_Ip  [kB * kC2 * kTx];            // (iv[2c], iv[2c+1]) per x
__device__ float2 g_A2p [kB * kC2 * kTx];            // (-2*mu*iv) pairs
__device__ float  g_bias[kB * kTx];
__device__ float  g_logpT[(size_t)kB * kTy * kTx + 40 * kTx];  // [b][t][x] + pad
__device__ int    g_cum [kB * 257];
__device__ int    g_xidx[kB * kTy];

#define FMA2(d,a,b,c) asm("fma.rn.f32x2 %0, %1, %2, %3;" : "=l"(d) : "l"(a), "l"(b), "l"(c))

// ---------------- Kernel 0: per-(b,x) precompute ------------------------------
__global__ void k_prep(const float* __restrict__ mu, const float* __restrict__ ls) {
    int b = blockIdx.x;
    int x = threadIdx.x;
    const float* mub = mu + (size_t)b * kC * kTx + x;
    const float* lsb = ls + (size_t)b * kC * kTx + x;
    float t3 = 0.f, sls = 0.f;
    #pragma unroll 4
    for (int c2 = 0; c2 < kC2; c2++) {
        float m0 = mub[(2 * c2) * kTx],     m1 = mub[(2 * c2 + 1) * kTx];
        float l0 = lsb[(2 * c2) * kTx],     l1 = lsb[(2 * c2 + 1) * kTx];
        float iv0 = expf(-2.0f * l0),       iv1 = expf(-2.0f * l1);
        g_Ip [(b * kC2 + c2) * kTx + x] = make_float2(iv0, iv1);
        g_A2p[(b * kC2 + c2) * kTx + x] = make_float2(-2.0f * m0 * iv0, -2.0f * m1 * iv1);
        t3  += m0 * m0 * iv0 + m1 * m1 * iv1;
        sls += l0 + l1;
    }
    g_bias[b * kTx + x] = -(0.5f / (float)kC) * (t3 + sls);
}

// ---------------- Kernel 1: logp GEMM (R8-exact, best measured 105.4us) --------
// Tile 64x × 128t per block, 256 threads = 16 x-groups(4x) × 16 t-groups(8t).
constexpr int SY_OFF  = 0;
constexpr int SI_OFF  = 40 * 160;
constexpr int SA_OFF  = SI_OFF + 40 * 80;
constexpr int SMEM_ULL = SA_OFF + 40 * 80;          // 12800 ull = 102400 B

__global__ void __launch_bounds__(256) k_logp(const float* __restrict__ y,
                                              float* __restrict__ out_logp) {
    extern __shared__ ull sm[];
    int b  = blockIdx.z;
    int x0 = blockIdx.y * 64;
    int t0 = blockIdx.x * 128;
    int tid = threadIdx.x;
    int tx = tid & 15;        // x-group (16 groups of 4 x)
    int ty = tid >> 4;        // t-group (16 groups of 8 t)

    for (int e = tid; e < 128 * kC2; e += 256) {
        int c2 = e % kC2;
        int t  = e / kC2;
        float2 v = *(const float2*)(y + ((size_t)(b * kTy + t0 + t)) * kC + 2 * c2);
        sm[SY_OFF + c2 * 160 + (t >> 3) * 10 + (t & 7)] = *(ull*)&v;
    }
    for (int e = tid; e < kC2 * 64; e += 256) {
        int c2 = e >> 6, xx = e & 63;
        int sidx = c2 * 80 + (xx >> 3) * 10 + (xx & 7);
        float2 vi = g_Ip [(b * kC2 + c2) * kTx + x0 + xx];
        float2 va = g_A2p[(b * kC2 + c2) * kTx + x0 + xx];
        sm[SI_OFF + sidx] = *(ull*)&vi;
        sm[SA_OFF + sidx] = *(ull*)&va;
    }
    __syncthreads();

    ull acc[4][8];
    #pragma unroll
    for (int i = 0; i < 4; i++)
        #pragma unroll
        for (int j = 0; j < 8; j++) acc[i][j] = 0ull;

    int txoff = ((tx * 4) >> 3) * 10 + ((tx * 4) & 7);

    #pragma unroll 2
    for (int c2 = 0; c2 < kC2; c2++) {
        ull ivp[4], a2p[4], yvp[8];
        const ulonglong2* pi = (const ulonglong2*)(sm + SI_OFF + c2 * 80 + txoff);
        const ulonglong2* pa = (const ulonglong2*)(sm + SA_OFF + c2 * 80 + txoff);
        const ulonglong2* py = (const ulonglong2*)(sm + SY_OFF + c2 * 160 + ty * 10);
        {
            ulonglong2 q;
            q = pi[0]; ivp[0] = q.x; ivp[1] = q.y;
            q = pi[1]; ivp[2] = q.x; ivp[3] = q.y;
            q = pa[0]; a2p[0] = q.x; a2p[1] = q.y;
            q = pa[1]; a2p[2] = q.x; a2p[3] = q.y;
        }
        #pragma unroll
        for (int i = 0; i < 4; i++) {
            ulonglong2 q = py[i];
            yvp[2 * i] = q.x; yvp[2 * i + 1] = q.y;
        }
        #pragma unroll
        for (int xi = 0; xi < 4; xi++)
            #pragma unroll
            for (int ti = 0; ti < 8; ti++) {
                ull tmp;
                FMA2(tmp, ivp[xi], yvp[ti], a2p[xi]);
                FMA2(acc[xi][ti], yvp[ti], tmp, acc[xi][ti]);
            }
    }

    const float SC = -0.5f / (float)kC;
    float res[4][8];
    #pragma unroll
    for (int xi = 0; xi < 4; xi++) {
        float bsv = g_bias[b * kTx + x0 + tx * 4 + xi];
        #pragma unroll
        for (int ti = 0; ti < 8; ti++) {
            float2 p = *(float2*)&acc[xi][ti];
            res[xi][ti] = __fmaf_rn(SC, p.x + p.y, bsv);
        }
    }
    #pragma unroll
    for (int xi = 0; xi < 4; xi++) {
        int x = x0 + tx * 4 + xi;
        float* o = out_logp + ((size_t)(b * kTx + x)) * kTy + t0 + ty * 8;
        float4 r;
        r.x = res[xi][0]; r.y = res[xi][1]; r.z = res[xi][2]; r.w = res[xi][3];
        __stcs((float4*)o, r);
        r.x = res[xi][4]; r.y = res[xi][5]; r.z = res[xi][6]; r.w = res[xi][7];
        __stcs((float4*)(o + 4), r);
    }
    #pragma unroll
    for (int ti = 0; ti < 8; ti++) {
        int t = t0 + ty * 8 + ti;
        float* o = g_logpT + ((size_t)b * kTy + t) * kTx + x0 + tx * 4;
        float4 r;
        r.x = res[0][ti]; r.y = res[1][ti]; r.z = res[2][ti]; r.w = res[3][ti];
        *(float4*)o = r;
    }
}

// ---------------- Kernel 2: MAS, 4-warp chunked-diagonal, chunk=128 (proven) ---
constexpr int SD_WORDS = 64 * kTx;
constexpr int BND_N    = 2056;

__global__ void __launch_bounds__(256) k_mas(const int* __restrict__ xlv,
                                             const int* __restrict__ ylv,
                                             float* __restrict__ dr_out) {
    extern __shared__ unsigned sdiag[];
    __shared__ float s_bnd[4][BND_N];
    __shared__ int s_dr[kTx];
    __shared__ int s_wsum[8];
    __shared__ int s_tot;
    int b = blockIdx.x;
    int tid = threadIdx.x;
    int w = tid >> 5, lane = tid & 31;

    s_dr[tid] = 0;
    for (int e = tid; e < BND_N; e += 256) s_bnd[3][e] = NEGV;
    if (tid < 3) s_bnd[tid][0] = NEGV;
    __syncthreads();

    float v0, v1, sh_next, bvn;
    float2 buf[32];
    unsigned bits0 = 0u, bits1 = 0u;
    const float* lp = nullptr;
    const float* cons = nullptr;
    bool doProd = false;
    int r0 = 0;

    if (w < 4) {
        r0 = w * 64 + lane * 2;
        lp = g_logpT + (size_t)b * kTy * kTx + r0;
        cons = (w == 0) ? s_bnd[3] : s_bnd[w - 1];
        doProd = (w < 3) && (lane == 31);
        v0 = (r0 == 0) ? 0.f : NEGV;
        v1 = NEGV;
        #pragma unroll
        for (int i = 0; i < 32; i++) buf[i] = *(const float2*)(lp + (size_t)i * kTx);
        sh_next = __shfl_up_sync(0xffffffffu, v1, 1);
        bvn = cons[0];
    }

    for (int p = 0; p < 19; p++) {
        int c = p - w;
        if (w < 4 && c >= 0 && c < 16) {
            int tbase = c * 128;
            for (int j0 = 0; j0 < 128; j0 += 32) {
                int tb = tbase + j0;
                #pragma unroll
                for (int jj = 0; jj < 32; jj++) {
                    int t = tb + jj;
                    float2 col = buf[jj];
                    buf[jj] = *(const float2*)(lp + (size_t)(t + 32) * kTx);
                    float bv = bvn;
                    bvn = cons[t + 1];
                    float pv0 = (lane == 0) ? bv : sh_next;
                    float pv1 = v0;
                    if (pv0 > v0) bits0 |= (1u << jj);
                    if (pv1 > v1) bits1 |= (1u << jj);
                    v0 = fmaxf(pv0, v0) + col.x;
                    v1 = fmaxf(pv1, v1) + col.y;
                    sh_next = __shfl_up_sync(0xffffffffu, v1, 1);
                    if (doProd) s_bnd[w][t + 1] = v1;
                }
                *(ull*)&sdiag[(tb >> 5) * kTx + r0] = (ull)bits0 | ((ull)bits1 << 32);
                bits0 = bits1 = 0u;
            }
        }
        __syncthreads();
    }

    if (tid == 0) {
        int xlen = xlv[b], ylen = ylv[b];
        int i = xlen - 1;
        int t = ylen - 1;
        while (i > 0 && t >= 0) {
            int wd = t >> 5;
            unsigned word = sdiag[wd * kTx + i] & (0xFFFFFFFFu >> (31 - (t & 31)));
            int tp = -1;
            while (true) {
                if (word) { tp = (wd << 5) + (31 - __clz(word)); break; }
                if (--wd < 0) break;
                word = sdiag[wd * kTx + i];
            }
            if (tp < 0) { s_dr[i] = t + 1; t = -1; break; }
            s_dr[i] = t - tp + 1;
            t = tp - 1;
            i--;
        }
        if (i == 0 && t >= 0) s_dr[0] = t + 1;
    }
    __syncthreads();

    int dv = s_dr[tid];
    int sl = tid & 31, sw = tid >> 5;
    int xs = dv;
    #pragma unroll
    for (int off = 1; off < 32; off <<= 1) {
        int n = __shfl_up_sync(0xffffffffu, xs, off);
        if (sl >= off) xs += n;
    }
    if (sl == 31) s_wsum[sw] = xs;
    __syncthreads();
    if (tid == 0) {
        int a = 0;
        #pragma unroll
        for (int q = 0; q < 8; q++) { int tmp = s_wsum[q]; s_wsum[q] = a; a += tmp; }
        s_tot = a;
    }
    __syncthreads();
    int incl = xs + s_wsum[sw];
    int excl = incl - dv;

    dr_out[b * kTx + tid] = (float)dv;
    g_cum[b * 257 + tid] = excl;
    if (tid == kTx - 1) g_cum[b * 257 + kTx] = incl;

    for (int t = excl; t < excl + dv; t++) g_xidx[b * kTy + t] = tid;
    int total = s_tot;
    for (int t = total + tid; t < kTy; t += 256) g_xidx[b * kTy + t] = -1;
}

// ---------------- Kernel 3: fused attn + o_en gather (proven) ------------------
__global__ void __launch_bounds__(256) k_post(const float* __restrict__ en,
                                              float* __restrict__ oex,
                                              float* __restrict__ attn) {
    int b = blockIdx.y;
    int tid = threadIdx.x;

    if (blockIdx.x < 32) {
        __shared__ __align__(16) float srow[8][kTx];
        __shared__ __align__(16) int   sidx[kTy];
        int h0 = blockIdx.x * 8;

        for (int e = tid; e < 8 * kTx; e += 256) {
            int hh = e >> 8, xx = e & 255;
            srow[hh][xx] = en[((size_t)(b * kH + h0 + hh)) * kTx + xx];
        }
        const int* xsrc = g_xidx + b * kTy;
        for (int e = tid; e < kTy; e += 256) sidx[e] = xsrc[e];
        __syncthreads();

        int4 ia = *(const int4*)&sidx[tid * 8];
        int4 ib = *(const int4*)&sidx[tid * 8 + 4];
        #pragma unroll
        for (int hh = 0; hh < 8; hh++) {
            float* o = oex + ((size_t)(b * kH + h0 + hh)) * kTy + tid * 8;
            const float* sr = srow[hh];
            float4 r;
            r.x = (ia.x >= 0) ? sr[ia.x] : 0.f;
            r.y = (ia.y >= 0) ? sr[ia.y] : 0.f;
            r.z = (ia.z >= 0) ? sr[ia.z] : 0.f;
            r.w = (ia.w >= 0) ? sr[ia.w] : 0.f;
            __stcs((float4*)o, r);
            r.x = (ib.x >= 0) ? sr[ib.x] : 0.f;
            r.y = (ib.y >= 0) ? sr[ib.y] : 0.f;
            r.z = (ib.z >= 0) ? sr[ib.z] : 0.f;
            r.w = (ib.w >= 0) ? sr[ib.w] : 0.f;
            __stcs((float4*)(o + 4), r);
        }
    } else {
        int seg = blockIdx.x - 32;
        int t = tid * 8;
        #pragma unroll 4
        for (int r = 0; r < 16; r++) {
            int x = seg * 16 + r;
            int lo = g_cum[b * 257 + x];
            int hi = g_cum[b * 257 + x + 1];
            float* o = attn + ((size_t)(b * kTx + x)) * kTy + t;
            float4 q;
            q.x = (t + 0 >= lo && t + 0 < hi) ? 1.f : 0.f;
            q.y = (t + 1 >= lo && t + 1 < hi) ? 1.f : 0.f;
            q.z = (t + 2 >= lo && t + 2 < hi) ? 1.f : 0.f;
            q.w = (t + 3 >= lo && t + 3 < hi) ? 1.f : 0.f;
            __stcs((float4*)o, q);
            q.x = (t + 4 >= lo && t + 4 < hi) ? 1.f : 0.f;
            q.y = (t + 5 >= lo && t + 5 < hi) ? 1.f : 0.f;
            q.z = (t + 6 >= lo && t + 6 < hi) ? 1.f : 0.f;
            q.w = (t + 7 >= lo && t + 7 < hi) ? 1.f : 0.f;
            __stcs((float4*)(o + 4), q);
        }
    }
}

// ---------------- launch --------------------------------------------------------
extern "C" void kernel_launch(void* const* d_in, const int* in_sizes, int n_in,
                              void* d_out, int out_size) {
    const float* en = (const float*)d_in[0];   // [B,H,Tx]
    const float* mu = (const float*)d_in[1];   // [B,C,Tx]
    const float* ls = (const float*)d_in[2];   // [B,C,Tx]
    const float* y  = (const float*)d_in[3];   // [B,Ty,C]
    const int*   xl = (const int*)d_in[4];     // [B]
    const int*   yl = (const int*)d_in[5];     // [B]

    float* out   = (float*)d_out;
    float* o_en  = out;                                     // B*H*Ty
    float* attn  = o_en + (size_t)kB * kH * kTy;            // B*Tx*Ty
    float* dr    = attn + (size_t)kB * kTx * kTy;           // B*Tx
    float* logp  = dr + (size_t)kB * kTx;                   // B*Tx*Ty

    cudaFuncSetAttribute(k_logp, cudaFuncAttributeMaxDynamicSharedMemorySize,
                         SMEM_ULL * 8);
    cudaFuncSetAttribute(k_mas, cudaFuncAttributeMaxDynamicSharedMemorySize,
                         SD_WORDS * 4);

    k_prep<<<kB, kTx>>>(mu, ls);
    k_logp<<<dim3(kTy / 128, kTx / 64, kB), 256, SMEM_ULL * 8>>>(y, logp);
    k_mas<<<kB, 256, SD_WORDS * 4>>>(xl, yl, dr);
    k_post<<<dim3(48, kB), 256>>>(en, o_en, attn);
}